// round 1
// baseline (speedup 1.0000x reference)
#include <cuda_runtime.h>
#include <math.h>

#define TOKS    8192
#define DMODEL  1024
#define FEXP    512
#define NEXP    16
#define NROUTED 14
#define KROUTE  4
#define KSEL    6

// ---------------- scratch (static device globals; no runtime allocation) ----
__device__ int   g_cnt[NEXP];
__device__ int   g_tok[NEXP * TOKS];
__device__ float g_aff[NEXP * TOKS];
__device__ float g_h[(size_t)NEXP * TOKS * FEXP];   // silu(xK)*aff, per (expert,slot)

// ---------------- utility kernels ------------------------------------------
__global__ void zero_out_kernel(float* out, int n) {
    int i = blockIdx.x * blockDim.x + threadIdx.x;
    if (i < n) out[i] = 0.f;
}

__global__ void zero_cnt_kernel() {
    if (threadIdx.x < NEXP) g_cnt[threadIdx.x] = 0;
}

// ---------------- routing ---------------------------------------------------
// one block (256 thr) per token: 16 dot products of length 1024, sigmoid,
// top-4 of first 14 (stable: strictly-greater keeps lowest index on ties,
// matching jax.lax.top_k), append to per-expert token lists.
__global__ __launch_bounds__(256) void routing_kernel(
    const float* __restrict__ sel_in,
    const float* __restrict__ expert_sel,
    const float* __restrict__ bias,
    float* __restrict__ out, int write_sel)
{
    const int t    = blockIdx.x;
    const int tid  = threadIdx.x;
    const int warp = tid >> 5, lane = tid & 31;
    __shared__ float logit[NEXP];

    const float* x = sel_in + (size_t)t * DMODEL;
    #pragma unroll
    for (int w = 0; w < 2; w++) {
        int e = warp * 2 + w;
        const float* wr = expert_sel + (size_t)e * DMODEL;
        float s = 0.f;
        for (int i = lane; i < DMODEL; i += 32) s += x[i] * wr[i];
        #pragma unroll
        for (int o = 16; o > 0; o >>= 1) s += __shfl_xor_sync(0xffffffffu, s, o);
        if (lane == 0) logit[e] = s;
    }
    __syncthreads();

    if (tid == 0) {
        float a[NEXP];
        #pragma unroll
        for (int e = 0; e < NEXP; e++) a[e] = 1.f / (1.f + expf(-logit[e]));

        int  sel[KSEL];
        float af[KSEL];
        bool taken[NROUTED];
        #pragma unroll
        for (int i = 0; i < NROUTED; i++) taken[i] = false;
        #pragma unroll
        for (int k = 0; k < KROUTE; k++) {
            float best = -1e30f; int bi = 0;
            for (int i = 0; i < NROUTED; i++) {
                float v = a[i] + bias[i];
                if (!taken[i] && v > best) { best = v; bi = i; }
            }
            taken[bi] = true; sel[k] = bi; af[k] = a[bi];
        }
        sel[4] = NROUTED;     af[4] = a[NROUTED];
        sel[5] = NROUTED + 1; af[5] = a[NROUTED + 1];

        #pragma unroll
        for (int k = 0; k < KSEL; k++) {
            int e   = sel[k];
            int pos = atomicAdd(&g_cnt[e], 1);
            g_tok[e * TOKS + pos] = t;
            g_aff[e * TOKS + pos] = af[k];
            if (write_sel)
                out[(size_t)TOKS * DMODEL + (size_t)t * KSEL + k] = (float)e;
        }
    }
}

// ---------------- grouped GEMM 1: H = silu(X_gathered @ K_e) * aff ----------
// tile 64 (tokens) x 64 (f), K-step 16, fp32, 4x4 per thread.
__global__ __launch_bounds__(256) void gemm1_kernel(
    const float* __restrict__ xs, const float* __restrict__ keys)
{
    const int e   = blockIdx.y;
    const int cnt = g_cnt[e];
    const int m0  = blockIdx.x * 64;
    if (m0 >= cnt) return;
    const int n0  = blockIdx.z * 64;

    __shared__ float As[16][64];   // [k][m]
    __shared__ float Bs[16][64];   // [k][n]
    __shared__ int   toks[64];
    __shared__ float affs[64];

    const int tid = threadIdx.x;
    if (tid < 64) {
        int mg = m0 + tid;
        toks[tid] = (mg < cnt) ? g_tok[e * TOKS + mg] : 0;
        affs[tid] = (mg < cnt) ? g_aff[e * TOKS + mg] : 0.f;
    }
    __syncthreads();

    const int ty  = tid >> 4, tx  = tid & 15;  // compute 4x4 at (ty*4, tx*4)
    const int am  = tid >> 2, akq = tid & 3;   // A loader: row am, k-quad akq
    const int bk  = tid >> 4, bnq = tid & 15;  // B loader: k row bk, n-quad bnq
    const bool avalid = (m0 + am) < cnt;
    const float* arow = xs + (size_t)toks[am] * DMODEL;

    float acc[4][4];
    #pragma unroll
    for (int i = 0; i < 4; i++)
        #pragma unroll
        for (int j = 0; j < 4; j++) acc[i][j] = 0.f;

    for (int k0 = 0; k0 < DMODEL; k0 += 16) {
        float4 av = avalid ? *(const float4*)(arow + k0 + akq * 4)
                           : make_float4(0.f, 0.f, 0.f, 0.f);
        float4 bv = *(const float4*)(keys +
                    ((size_t)e * DMODEL + k0 + bk) * FEXP + n0 + bnq * 4);
        As[akq * 4 + 0][am] = av.x;
        As[akq * 4 + 1][am] = av.y;
        As[akq * 4 + 2][am] = av.z;
        As[akq * 4 + 3][am] = av.w;
        *(float4*)&Bs[bk][bnq * 4] = bv;
        __syncthreads();
        #pragma unroll
        for (int kk = 0; kk < 16; kk++) {
            float4 a = *(const float4*)&As[kk][ty * 4];
            float4 b = *(const float4*)&Bs[kk][tx * 4];
            float ar[4] = {a.x, a.y, a.z, a.w};
            float br[4] = {b.x, b.y, b.z, b.w};
            #pragma unroll
            for (int i = 0; i < 4; i++)
                #pragma unroll
                for (int j = 0; j < 4; j++) acc[i][j] += ar[i] * br[j];
        }
        __syncthreads();
    }

    const size_t hbase = ((size_t)e * TOKS + m0) * FEXP + n0;
    #pragma unroll
    for (int i = 0; i < 4; i++) {
        int m = ty * 4 + i;
        if (m0 + m < cnt) {
            float afv = affs[m];
            #pragma unroll
            for (int j = 0; j < 4; j++) {
                float v = acc[i][j];
                float s = v / (1.f + __expf(-v));   // silu
                g_h[hbase + (size_t)m * FEXP + tx * 4 + j] = s * afv;
            }
        }
    }
}

// ---------------- grouped GEMM 2: out[tok] += H @ V_e -----------------------
__global__ __launch_bounds__(256) void gemm2_kernel(
    const float* __restrict__ values, float* __restrict__ out)
{
    const int e   = blockIdx.y;
    const int cnt = g_cnt[e];
    const int m0  = blockIdx.x * 64;
    if (m0 >= cnt) return;
    const int n0  = blockIdx.z * 64;

    __shared__ float As[16][64];
    __shared__ float Bs[16][64];
    __shared__ int   toks[64];

    const int tid = threadIdx.x;
    if (tid < 64) {
        int mg = m0 + tid;
        toks[tid] = (mg < cnt) ? g_tok[e * TOKS + mg] : 0;
    }
    __syncthreads();

    const int ty  = tid >> 4, tx  = tid & 15;
    const int am  = tid >> 2, akq = tid & 3;
    const int bk  = tid >> 4, bnq = tid & 15;
    const bool avalid = (m0 + am) < cnt;
    const float* arow = g_h + ((size_t)e * TOKS + m0 + am) * FEXP;

    float acc[4][4];
    #pragma unroll
    for (int i = 0; i < 4; i++)
        #pragma unroll
        for (int j = 0; j < 4; j++) acc[i][j] = 0.f;

    for (int k0 = 0; k0 < FEXP; k0 += 16) {
        float4 av = avalid ? *(const float4*)(arow + k0 + akq * 4)
                           : make_float4(0.f, 0.f, 0.f, 0.f);
        float4 bv = *(const float4*)(values +
                    ((size_t)e * FEXP + k0 + bk) * DMODEL + n0 + bnq * 4);
        As[akq * 4 + 0][am] = av.x;
        As[akq * 4 + 1][am] = av.y;
        As[akq * 4 + 2][am] = av.z;
        As[akq * 4 + 3][am] = av.w;
        *(float4*)&Bs[bk][bnq * 4] = bv;
        __syncthreads();
        #pragma unroll
        for (int kk = 0; kk < 16; kk++) {
            float4 a = *(const float4*)&As[kk][ty * 4];
            float4 b = *(const float4*)&Bs[kk][tx * 4];
            float ar[4] = {a.x, a.y, a.z, a.w};
            float br[4] = {b.x, b.y, b.z, b.w};
            #pragma unroll
            for (int i = 0; i < 4; i++)
                #pragma unroll
                for (int j = 0; j < 4; j++) acc[i][j] += ar[i] * br[j];
        }
        __syncthreads();
    }

    #pragma unroll
    for (int i = 0; i < 4; i++) {
        int m = ty * 4 + i;
        if (m0 + m < cnt) {
            int t = toks[m];
            #pragma unroll
            for (int j = 0; j < 4; j++)
                atomicAdd(&out[(size_t)t * DMODEL + n0 + tx * 4 + j], acc[i][j]);
        }
    }
}

// ---------------- launch -----------------------------------------------------
extern "C" void kernel_launch(void* const* d_in, const int* in_sizes, int n_in,
                              void* d_out, int out_size) {
    const float* token_stream = (const float*)d_in[0];
    const float* sel_input    = (const float*)d_in[1];
    const float* keys         = (const float*)d_in[2];
    const float* values       = (const float*)d_in[3];
    const float* esel         = (const float*)d_in[4];
    const float* bias         = (const float*)d_in[5];
    float* out = (float*)d_out;

    const int write_sel = (out_size >= TOKS * DMODEL + TOKS * KSEL) ? 1 : 0;

    zero_out_kernel<<<(TOKS * DMODEL + 511) / 512, 512>>>(out, TOKS * DMODEL);
    zero_cnt_kernel<<<1, 32>>>();
    routing_kernel<<<TOKS, 256>>>(sel_input, esel, bias, out, write_sel);

    dim3 g1(TOKS / 64, NEXP, FEXP / 64);
    gemm1_kernel<<<g1, 256>>>(token_stream, keys);

    dim3 g2(TOKS / 64, NEXP, DMODEL / 64);
    gemm2_kernel<<<g2, 256>>>(values, out);
}